// round 11
// baseline (speedup 1.0000x reference)
#include <cuda_runtime.h>
#include <cuda_bf16.h>
#include <cstdint>

#define BB 256
#define NN 512
#define DD 6
#define FF 128
#define MAXDEG 6
#define BN (BB * NN)
#define TM 128
#define SSTR 136      // W smem row stride in bf16 (128+8); 272B
#define KSTR 72       // S-chunk smem row stride in bf16 (64+8); 144B
#define SLOTS (BN + MAXDEG * TM)

// ---- smem byte offsets ----
#define SM_WH   0                        // 128 x SSTR bf16 = 34816B
#define SM_WL   34816
#define SM_SH   69632                    // 128 x KSTR bf16 = 18432B (64-k chunk)
#define SM_SL   88064
#define SM_NODE 106496                   // 128 ints
#define SM_BIAS 107008                   // 128 floats
#define SM_BYTES 107520

// ---- device scratch ----
__device__ int g_list[MAXDEG * BN];
__device__ int g_cnt[MAXDEG];
__device__ int g_ps[MAXDEG + 1];
__device__ int g_node[SLOTS];
__device__ __nv_bfloat16 g_sh[(size_t)SLOTS * FF];
__device__ __nv_bfloat16 g_sl[(size_t)SLOTS * FF];
__device__ __nv_bfloat16 g_wh[MAXDEG * FF * FF];   // W^T hi: [d][n][k]
__device__ __nv_bfloat16 g_wl[MAXDEG * FF * FF];

__device__ __forceinline__ uint32_t smem_u32(const void* p) {
    uint32_t a;
    asm("{ .reg .u64 t; cvta.to.shared.u64 t, %1; cvt.u32.u64 %0, t; }" : "=r"(a) : "l"(p));
    return a;
}
__device__ __forceinline__ void cpa16(uint32_t dst, const void* src) {
    asm volatile("cp.async.cg.shared.global [%0], [%1], 16;" :: "r"(dst), "l"(src));
}
#define CPA_COMMIT() asm volatile("cp.async.commit_group;" ::: "memory")
#define CPA_WAIT0()  asm volatile("cp.async.wait_group 0;" ::: "memory")

__device__ __forceinline__ void ldm_x4(uint32_t& r0, uint32_t& r1, uint32_t& r2, uint32_t& r3,
                                       uint32_t addr) {
    asm volatile("ldmatrix.sync.aligned.m8n8.x4.shared.b16 {%0,%1,%2,%3}, [%4];"
                 : "=r"(r0), "=r"(r1), "=r"(r2), "=r"(r3) : "r"(addr));
}
__device__ __forceinline__ void mma16816(float* c, const uint32_t* a, uint32_t b0, uint32_t b1) {
    asm volatile("mma.sync.aligned.m16n8k16.row.col.f32.bf16.bf16.f32 "
                 "{%0,%1,%2,%3}, {%4,%5,%6,%7}, {%8,%9}, {%0,%1,%2,%3};"
                 : "+f"(c[0]), "+f"(c[1]), "+f"(c[2]), "+f"(c[3])
                 : "r"(a[0]), "r"(a[1]), "r"(a[2]), "r"(a[3]), "r"(b0), "r"(b1));
}

// ===================== kernel 1: W split/transpose (+zero counters) =====
__global__ void k_wsplit(const float* __restrict__ W) {
    int i = blockIdx.x * blockDim.x + threadIdx.x;   // < 6*128*128
    if (blockIdx.x == 0 && threadIdx.x < MAXDEG) g_cnt[threadIdx.x] = 0;
    int d = i >> 14, rem = i & 16383, k = rem >> 7, n = rem & 127;
    float v = W[i];                                  // W[d][k][n]
    __nv_bfloat16 hi = __float2bfloat16(v);
    float lo = v - __bfloat162float(hi);
    int o = (d << 14) + (n << 7) + k;                // W^T[d][n][k]
    g_wh[o] = hi;
    g_wl[o] = __float2bfloat16(lo);
}

// ===================== kernel 2: bucket nodes by degree ============
__global__ void k_bucket(const int* __restrict__ edges) {
    __shared__ int c[MAXDEG];
    __shared__ int base[MAXDEG];
    int t = threadIdx.x;                    // 512 threads
    if (t < MAXDEG) c[t] = 0;
    __syncthreads();
    int node = blockIdx.x * 512 + t;
    int deg = 0;
#pragma unroll
    for (int s = 0; s < DD; s++) deg += (edges[node * DD + s] >= 0);
    if (deg >= MAXDEG) deg = MAXDEG - 1;
    int pos = atomicAdd(&c[deg], 1);
    __syncthreads();
    if (t < MAXDEG) base[t] = atomicAdd(&g_cnt[t], c[t]);
    __syncthreads();
    g_list[deg * BN + base[deg] + pos] = node;
}

// ===================== kernel 3: padded prefix offsets ============
__global__ void k_prefix() {
    if (threadIdx.x == 0) {
        int off = 0;
#pragma unroll
        for (int d = 0; d < MAXDEG; d++) {
            g_ps[d] = off;
            off += (g_cnt[d] + TM - 1) & ~(TM - 1);
        }
        g_ps[MAXDEG] = off;
    }
}

// ===================== kernel 4: gather+sum -> compact bf16 S ======
__global__ __launch_bounds__(256)
void k_gather(const float* __restrict__ atoms, const int* __restrict__ edges) {
    int gw = (blockIdx.x * 256 + threadIdx.x) >> 5;
    int lane = threadIdx.x & 31;
    if (gw >= g_ps[MAXDEG]) return;
    int d = 0;
#pragma unroll
    for (int t = 1; t < MAXDEG; t++) if (gw >= g_ps[t]) d = t;
    int i = gw - g_ps[d];
    if (i >= g_cnt[d]) return;

    int node = g_list[d * BN + i];
    if (lane == 0) g_node[gw] = node;

    const float4* A = (const float4*)atoms;
    float4 acc = A[node * 32 + lane];
    int nb = (node >> 9) << 9;
    int eb = node * DD;
#pragma unroll
    for (int s = 0; s < DD; s++) {
        int e = edges[eb + s];
        if (e >= 0) {
            e = (e < NN) ? e : 0;
            float4 v = A[(nb + e) * 32 + lane];
            acc.x += v.x; acc.y += v.y; acc.z += v.z; acc.w += v.w;
        }
    }
    float vals[4] = {acc.x, acc.y, acc.z, acc.w};
    uint32_t hp[2], lp[2];
#pragma unroll
    for (int j = 0; j < 2; j++) {
        float v0 = vals[2 * j], v1 = vals[2 * j + 1];
        __nv_bfloat16 h0 = __float2bfloat16(v0);
        __nv_bfloat16 h1 = __float2bfloat16(v1);
        __nv_bfloat16 l0 = __float2bfloat16(v0 - __bfloat162float(h0));
        __nv_bfloat16 l1 = __float2bfloat16(v1 - __bfloat162float(h1));
        hp[j] = ((uint32_t)__bfloat16_as_ushort(h1) << 16) | __bfloat16_as_ushort(h0);
        lp[j] = ((uint32_t)__bfloat16_as_ushort(l1) << 16) | __bfloat16_as_ushort(l0);
    }
    ((uint2*)g_sh)[(size_t)gw * 32 + lane] = make_uint2(hp[0], hp[1]);
    ((uint2*)g_sl)[(size_t)gw * 32 + lane] = make_uint2(lp[0], lp[1]);
}

// ===================== kernel 5: HMMA GEMM, 32x64 warp tiles =======
// 8 warps: wid&3 -> row group (32 rows), wid>>2 -> col group (64 cols)
__global__ __launch_bounds__(256, 2)
void k_mma(const float* __restrict__ bias, float* __restrict__ out) {
    const int tileBase = blockIdx.x * TM;
    int d = 0;
#pragma unroll
    for (int t = 1; t < MAXDEG; t++) if (tileBase >= g_ps[t]) d = t;
    const int pe = g_ps[d] + g_cnt[d];
    if (tileBase >= pe) return;

    extern __shared__ char smc[];
    const uint32_t sb = smem_u32(smc);
    const int tid = threadIdx.x;
    const int wid = tid >> 5;
    const int lid = tid & 31;

    int*   snode = (int*)(smc + SM_NODE);
    float* sbias = (float*)(smc + SM_BIAS);
    if (tid < TM) {
        snode[tid] = g_node[tileBase + tid];
        sbias[tid] = bias[d * FF + tid];
    }

    // ---- stage W (full, hi+lo) + S k-chunk 0 via cp.async
    const char* whp = (const char*)(g_wh + (d << 14));
    const char* wlp = (const char*)(g_wl + (d << 14));
    for (int i = tid; i < FF * 16; i += 256) {           // 128 rows x 16 16B-chunks
        int row = i >> 4, ch = (i & 15) * 16;
        uint32_t dsto = (uint32_t)row * (SSTR * 2) + ch;
        cpa16(sb + SM_WH + dsto, whp + row * 256 + ch);
        cpa16(sb + SM_WL + dsto, wlp + row * 256 + ch);
    }
    const char* shp = (const char*)g_sh + (size_t)tileBase * 256;
    const char* slp = (const char*)g_sl + (size_t)tileBase * 256;
    for (int i = tid; i < TM * 8; i += 256) {            // 128 rows x 8 16B-chunks (64 k)
        int row = i >> 3, ch = (i & 7) * 16;
        uint32_t dsto = (uint32_t)row * (KSTR * 2) + ch;
        cpa16(sb + SM_SH + dsto, shp + row * 256 + ch);
        cpa16(sb + SM_SL + dsto, slp + row * 256 + ch);
    }
    CPA_COMMIT();

    // ---- lane-invariant addressing ----
    const int rg = wid & 3;                 // row group: rows rg*32 .. +31
    const int cg = wid >> 2;                // col group: cols cg*64 .. +63
    // A frag lane pattern (within a 16x16 block)
    const uint32_t alo = (uint32_t)(((lid & 7) + ((lid >> 3) & 1) * 8) * KSTR
                                    + ((lid >> 4) & 1) * 8) * 2;
    const uint32_t arowb0 = (uint32_t)(rg * 32) * (KSTR * 2);
    // B frag lane pattern
    const int bnl  = (lid & 7) + ((lid >> 4) & 1) * 8;
    const int bk   = ((lid >> 3) & 1) * 8;

    float acc[16][4];                       // [half*8 + p*2 + j][q]
#pragma unroll
    for (int t = 0; t < 16; t++)
#pragma unroll
        for (int q = 0; q < 4; q++) acc[t][q] = 0.f;

    CPA_WAIT0();
    __syncthreads();

#pragma unroll
    for (int kc = 0; kc < 2; kc++) {
        if (kc == 1) {
            __syncthreads();                // all warps done reading chunk 0
            for (int i = tid; i < TM * 8; i += 256) {
                int row = i >> 3, ch = (i & 7) * 16;
                uint32_t dsto = (uint32_t)row * (KSTR * 2) + ch;
                cpa16(sb + SM_SH + dsto, shp + row * 256 + 128 + ch);
                cpa16(sb + SM_SL + dsto, slp + row * 256 + 128 + ch);
            }
            CPA_COMMIT();
            CPA_WAIT0();
            __syncthreads();
        }
#pragma unroll
        for (int kb = 0; kb < 4; kb++) {
            const uint32_t ak = (uint32_t)kb * 32;            // 16 bf16 in S chunk
            const uint32_t wk = (uint32_t)(kc * 64 + kb * 16 + bk) * 2;
            uint32_t ah0[4], ah1[4], al0[4], al1[4];
            ldm_x4(ah0[0], ah0[1], ah0[2], ah0[3], sb + SM_SH + arowb0 + alo + ak);
            ldm_x4(ah1[0], ah1[1], ah1[2], ah1[3], sb + SM_SH + arowb0 + 16 * (KSTR * 2) + alo + ak);
            ldm_x4(al0[0], al0[1], al0[2], al0[3], sb + SM_SL + arowb0 + alo + ak);
            ldm_x4(al1[0], al1[1], al1[2], al1[3], sb + SM_SL + arowb0 + 16 * (KSTR * 2) + alo + ak);
#pragma unroll
            for (int p = 0; p < 4; p++) {
                uint32_t boff = (uint32_t)((cg * 64 + p * 16 + bnl) * (SSTR * 2)) + wk;
                uint32_t bh0, bh1, bh2, bh3, bl0, bl1, bl2, bl3;
                ldm_x4(bh0, bh1, bh2, bh3, sb + SM_WH + boff);
                ldm_x4(bl0, bl1, bl2, bl3, sb + SM_WL + boff);
                float* a00 = acc[p * 2];
                float* a01 = acc[p * 2 + 1];
                float* a10 = acc[8 + p * 2];
                float* a11 = acc[8 + p * 2 + 1];
                mma16816(a00, ah0, bh0, bh1);
                mma16816(a01, ah0, bh2, bh3);
                mma16816(a10, ah1, bh0, bh1);
                mma16816(a11, ah1, bh2, bh3);
                mma16816(a00, ah0, bl0, bl1);
                mma16816(a01, ah0, bl2, bl3);
                mma16816(a10, ah1, bl0, bl1);
                mma16816(a11, ah1, bl2, bl3);
                mma16816(a00, al0, bh0, bh1);
                mma16816(a01, al0, bh2, bh3);
                mma16816(a10, al1, bh0, bh1);
                mma16816(a11, al1, bh2, bh3);
            }
        }
    }

    // ---- epilogue: bias + relu + scatter
    const int cb = (lid & 3) * 2;
#pragma unroll
    for (int half = 0; half < 2; half++) {
        int r0 = rg * 32 + half * 16 + (lid >> 2);
        int r1 = r0 + 8;
        bool ok0 = (tileBase + r0) < pe;
        bool ok1 = (tileBase + r1) < pe;
        float* op0 = out + (size_t)snode[r0] * FF;
        float* op1 = out + (size_t)snode[r1] * FF;
#pragma unroll
        for (int p = 0; p < 4; p++) {
#pragma unroll
            for (int j = 0; j < 2; j++) {
                int c = cg * 64 + p * 16 + j * 8 + cb;
                float b0 = sbias[c], b1 = sbias[c + 1];
                float* a = acc[half * 8 + p * 2 + j];
                if (ok0) {
                    float x0 = fmaxf(a[0] + b0, 0.f);
                    float x1 = fmaxf(a[1] + b1, 0.f);
                    *(float2*)(op0 + c) = make_float2(x0, x1);
                }
                if (ok1) {
                    float x2 = fmaxf(a[2] + b0, 0.f);
                    float x3 = fmaxf(a[3] + b1, 0.f);
                    *(float2*)(op1 + c) = make_float2(x2, x3);
                }
            }
        }
    }
}

// ===================== launch =====================
extern "C" void kernel_launch(void* const* d_in, const int* in_sizes, int n_in,
                              void* d_out, int out_size) {
    const float* atoms = (const float*)d_in[0];
    const int*   edges = (const int*)d_in[1];
    const float* W     = (const float*)d_in[2];
    const float* bias  = (const float*)d_in[3];
    float*       out   = (float*)d_out;

    cudaFuncSetAttribute(k_mma, cudaFuncAttributeMaxDynamicSharedMemorySize, SM_BYTES);

    k_wsplit<<<(MAXDEG * FF * FF) / 256, 256>>>(W);   // also zeros g_cnt
    k_bucket<<<BN / 512, 512>>>(edges);
    k_prefix<<<1, 32>>>();
    k_gather<<<(SLOTS + 7) / 8, 256>>>(atoms, edges);
    k_mma<<<SLOTS / TM, 256, SM_BYTES>>>(bias, out);
}

// round 16
// speedup vs baseline: 1.0892x; 1.0892x over previous
#include <cuda_runtime.h>
#include <cuda_bf16.h>
#include <cstdint>

#define BB 256
#define NN 512
#define DD 6
#define FF 128
#define MAXDEG 6
#define BN (BB * NN)
#define TM 128
#define SSTR 136        // W smem row stride in bf16 (128+8); 272B
#define SLOTS (BN + MAXDEG * TM)
#define G_PER_DEG 49
#define MMA_CTAS (G_PER_DEG * MAXDEG)   // 294

// S chunk buffers: 32-k chunks, row stride 80B (40 bf16), conflict-free for ldmatrix
#define SROW 80
#define SBUF 20480      // one buffer: hi 128x80 + lo 128x80

// ---- smem byte offsets ----
#define SM_WH   0                        // 128 x SSTR bf16 = 34816B
#define SM_WL   34816
#define SM_S    69632                    // 2 buffers x 20480B
#define SM_NODE 110592                   // 128 ints
#define SM_BIAS 111104                   // 128 floats
#define SM_BYTES 111616

// ---- device scratch ----
__device__ int g_list[MAXDEG * BN];
__device__ int g_cnt[MAXDEG];
__device__ int g_node[SLOTS];
__device__ __nv_bfloat16 g_sh[(size_t)SLOTS * FF];
__device__ __nv_bfloat16 g_sl[(size_t)SLOTS * FF];
__device__ __nv_bfloat16 g_wh[MAXDEG * FF * FF];   // W^T hi: [d][n][k]
__device__ __nv_bfloat16 g_wl[MAXDEG * FF * FF];

__device__ __forceinline__ uint32_t smem_u32(const void* p) {
    uint32_t a;
    asm("{ .reg .u64 t; cvta.to.shared.u64 t, %1; cvt.u32.u64 %0, t; }" : "=r"(a) : "l"(p));
    return a;
}
__device__ __forceinline__ void cpa16(uint32_t dst, const void* src) {
    asm volatile("cp.async.cg.shared.global [%0], [%1], 16;" :: "r"(dst), "l"(src));
}
#define CPA_COMMIT() asm volatile("cp.async.commit_group;" ::: "memory")
#define CPA_WAIT(n)  asm volatile("cp.async.wait_group %0;" :: "n"(n) : "memory")

__device__ __forceinline__ void ldm_x4(uint32_t& r0, uint32_t& r1, uint32_t& r2, uint32_t& r3,
                                       uint32_t addr) {
    asm volatile("ldmatrix.sync.aligned.m8n8.x4.shared.b16 {%0,%1,%2,%3}, [%4];"
                 : "=r"(r0), "=r"(r1), "=r"(r2), "=r"(r3) : "r"(addr));
}
__device__ __forceinline__ void mma16816(float* c, const uint32_t* a, uint32_t b0, uint32_t b1) {
    asm volatile("mma.sync.aligned.m16n8k16.row.col.f32.bf16.bf16.f32 "
                 "{%0,%1,%2,%3}, {%4,%5,%6,%7}, {%8,%9}, {%0,%1,%2,%3};"
                 : "+f"(c[0]), "+f"(c[1]), "+f"(c[2]), "+f"(c[3])
                 : "r"(a[0]), "r"(a[1]), "r"(a[2]), "r"(a[3]), "r"(b0), "r"(b1));
}
__device__ __forceinline__ void split2(float v0, float v1, uint32_t& hp, uint32_t& lp) {
    __nv_bfloat16 h0 = __float2bfloat16(v0);
    __nv_bfloat16 h1 = __float2bfloat16(v1);
    __nv_bfloat16 l0 = __float2bfloat16(v0 - __bfloat162float(h0));
    __nv_bfloat16 l1 = __float2bfloat16(v1 - __bfloat162float(h1));
    hp = ((uint32_t)__bfloat16_as_ushort(h1) << 16) | __bfloat16_as_ushort(h0);
    lp = ((uint32_t)__bfloat16_as_ushort(l1) << 16) | __bfloat16_as_ushort(l0);
}

// ===================== kernel 1: bucket + W split (fused) ==========
// blocks [0,256): degree bucketing; blocks [256,448): W split/transpose
__global__ void k_prep(const int* __restrict__ edges, const float* __restrict__ W) {
    int t = threadIdx.x;                 // 512 threads
    if (blockIdx.x < 256) {
        __shared__ int c[MAXDEG];
        __shared__ int base[MAXDEG];
        if (t < MAXDEG) c[t] = 0;
        __syncthreads();
        int node = blockIdx.x * 512 + t;
        int deg = 0;
#pragma unroll
        for (int s = 0; s < DD; s++) deg += (edges[node * DD + s] >= 0);
        if (deg >= MAXDEG) deg = MAXDEG - 1;
        int pos = atomicAdd(&c[deg], 1);
        __syncthreads();
        if (t < MAXDEG) base[t] = atomicAdd(&g_cnt[t], c[t]);
        __syncthreads();
        g_list[deg * BN + base[deg] + pos] = node;
    } else {
        int i = (blockIdx.x - 256) * 512 + t;          // < 98304
        int d = i >> 14, rem = i & 16383, k = rem >> 7, n = rem & 127;
        float v = W[i];                                 // W[d][k][n]
        __nv_bfloat16 hi = __float2bfloat16(v);
        float lo = v - __bfloat162float(hi);
        int o = (d << 14) + (n << 7) + k;               // W^T[d][n][k]
        g_wh[o] = hi;
        g_wl[o] = __float2bfloat16(lo);
    }
}

// ===================== kernel 2: gather+sum, 2 slots per warp ======
__global__ __launch_bounds__(256)
void k_gather(const float* __restrict__ atoms, const int* __restrict__ edges) {
    const int warp = (blockIdx.x * 256 + threadIdx.x) >> 5;
    const int lane = threadIdx.x & 31;

    int cnts[MAXDEG], ps[MAXDEG + 1];
    ps[0] = 0;
#pragma unroll
    for (int t = 0; t < MAXDEG; t++) {
        cnts[t] = g_cnt[t];
        ps[t + 1] = ps[t] + ((cnts[t] + 127) & ~127);
    }
    const int gw0 = warp * 2, gw1 = gw0 + 1;
    int d0 = -1, d1 = -1;
#pragma unroll
    for (int t = 0; t < MAXDEG; t++) {
        if (gw0 >= ps[t] && gw0 < ps[t] + cnts[t]) d0 = t;
        if (gw1 >= ps[t] && gw1 < ps[t] + cnts[t]) d1 = t;
    }
    const bool v0 = d0 >= 0, v1 = d1 >= 0;
    if (!v0 && !v1) return;
    int n0 = 0, n1 = 0;
    if (v0) n0 = g_list[d0 * BN + (gw0 - ps[d0])];
    if (v1) n1 = g_list[d1 * BN + (gw1 - ps[d1])];
    if (lane == 0) {
        if (v0) g_node[gw0] = n0;
        if (v1) g_node[gw1] = n1;
    }

    int e0[DD], e1[DD];
#pragma unroll
    for (int s = 0; s < DD; s++) {
        e0[s] = v0 ? edges[n0 * DD + s] : -1;
        e1[s] = v1 ? edges[n1 * DD + s] : -1;
    }
    const float4* A = (const float4*)atoms;
    float4 acc0 = v0 ? A[n0 * 32 + lane] : make_float4(0.f, 0.f, 0.f, 0.f);
    float4 acc1 = v1 ? A[n1 * 32 + lane] : make_float4(0.f, 0.f, 0.f, 0.f);
    const int nb0 = (n0 >> 9) << 9, nb1 = (n1 >> 9) << 9;
#pragma unroll
    for (int s = 0; s < DD; s++) {
        if (e0[s] >= 0) {
            int e = (e0[s] < NN) ? e0[s] : 0;
            float4 v = A[(nb0 + e) * 32 + lane];
            acc0.x += v.x; acc0.y += v.y; acc0.z += v.z; acc0.w += v.w;
        }
        if (e1[s] >= 0) {
            int e = (e1[s] < NN) ? e1[s] : 0;
            float4 v = A[(nb1 + e) * 32 + lane];
            acc1.x += v.x; acc1.y += v.y; acc1.z += v.z; acc1.w += v.w;
        }
    }
    uint32_t hp0, lp0, hp1, lp1;
    if (v0) {
        split2(acc0.x, acc0.y, hp0, lp0);
        split2(acc0.z, acc0.w, hp1, lp1);
        ((uint2*)g_sh)[(size_t)gw0 * 32 + lane] = make_uint2(hp0, hp1);
        ((uint2*)g_sl)[(size_t)gw0 * 32 + lane] = make_uint2(lp0, lp1);
    }
    if (v1) {
        split2(acc1.x, acc1.y, hp0, lp0);
        split2(acc1.z, acc1.w, hp1, lp1);
        ((uint2*)g_sh)[(size_t)gw1 * 32 + lane] = make_uint2(hp0, hp1);
        ((uint2*)g_sl)[(size_t)gw1 * 32 + lane] = make_uint2(lp0, lp1);
    }
}

// ===================== kernel 3: persistent HMMA GEMM ==============
// 294 CTAs: blockIdx/49 -> degree (W staged once), rank = blockIdx%49 strides tiles.
// 8 warps: wid&3 -> 32-row group, wid>>2 -> 64-col group. S: double-buffered 32-k chunks.
__global__ __launch_bounds__(256, 2)
void k_mma(const float* __restrict__ bias, float* __restrict__ out) {
    const int d = blockIdx.x / G_PER_DEG;
    const int rank = blockIdx.x % G_PER_DEG;
    int ps_d = 0, cnt = 0;
#pragma unroll
    for (int t = 0; t < MAXDEG; t++) {
        int c = g_cnt[t];
        if (t < d) ps_d += (c + 127) & ~127;
        if (t == d) cnt = c;
    }
    const int ntiles = (cnt + 127) >> 7;
    if (rank >= ntiles) return;
    const int pe = ps_d + cnt;

    extern __shared__ char smc[];
    const uint32_t sb = smem_u32(smc);
    const int tid = threadIdx.x, wid = tid >> 5, lid = tid & 31;
    int*   snode = (int*)(smc + SM_NODE);
    float* sbias = (float*)(smc + SM_BIAS);
    if (tid < TM) sbias[tid] = bias[d * FF + tid];

    // ---- stage W hi/lo once (persistent for this CTA)
    const char* whp = (const char*)(g_wh + (d << 14));
    const char* wlp = (const char*)(g_wl + (d << 14));
    for (int i = tid; i < FF * 16; i += 256) {
        int row = i >> 4, ch = (i & 15) * 16;
        uint32_t dsto = (uint32_t)row * (SSTR * 2) + ch;
        cpa16(sb + SM_WH + dsto, whp + row * 256 + ch);
        cpa16(sb + SM_WL + dsto, wlp + row * 256 + ch);
    }
    CPA_COMMIT();
    CPA_WAIT(0);

    // ---- lane-invariant addressing
    const int rg = wid & 3, cg = wid >> 2;
    const uint32_t alo = (uint32_t)((lid & 15) * SROW + ((lid >> 4) & 1) * 16);
    const uint32_t arow0 = (uint32_t)(rg * 32) * SROW;
    const int bnl = (lid & 7) + ((lid >> 4) & 1) * 8;
    const int bk  = ((lid >> 3) & 1) * 8;
    const int cb  = (lid & 3) * 2;

    for (int m = rank; m < ntiles; m += G_PER_DEG) {
        const int tb = ps_d + (m << 7);
        __syncthreads();                       // prev tile's buffer reads done
        if (tid < TM) snode[tid] = g_node[tb + tid];
        const char* shp = (const char*)g_sh + (size_t)tb * 256;
        const char* slp = (const char*)g_sl + (size_t)tb * 256;

        // prime chunks 0,1 into buffers 0,1
#pragma unroll
        for (int c0 = 0; c0 < 2; c0++) {
            uint32_t dst = sb + SM_S + c0 * SBUF;
            for (int i = tid; i < 512; i += 256) {
                int row = i >> 2, ch = (i & 3) * 16;
                cpa16(dst + row * SROW + ch, shp + row * 256 + c0 * 64 + ch);
                cpa16(dst + SBUF / 2 + row * SROW + ch, slp + row * 256 + c0 * 64 + ch);
            }
            CPA_COMMIT();
        }

        float acc[16][4];
#pragma unroll
        for (int t = 0; t < 16; t++)
#pragma unroll
            for (int q = 0; q < 4; q++) acc[t][q] = 0.f;

#pragma unroll
        for (int c = 0; c < 4; c++) {
            if (c < 3) CPA_WAIT(1); else CPA_WAIT(0);
            __syncthreads();
            const uint32_t sbuf = sb + SM_S + (uint32_t)(c & 1) * SBUF;
#pragma unroll
            for (int ks = 0; ks < 2; ks++) {
                const uint32_t ak = (uint32_t)ks * 32;          // 16 bf16 = 32B
                const uint32_t wk = (uint32_t)((c * 32 + ks * 16 + bk) * 2);
                uint32_t ah0[4], ah1[4], al0[4], al1[4];
                ldm_x4(ah0[0], ah0[1], ah0[2], ah0[3], sbuf + arow0 + alo + ak);
                ldm_x4(ah1[0], ah1[1], ah1[2], ah1[3], sbuf + arow0 + 16 * SROW + alo + ak);
                ldm_x4(al0[0], al0[1], al0[2], al0[3], sbuf + SBUF / 2 + arow0 + alo + ak);
                ldm_x4(al1[0], al1[1], al1[2], al1[3], sbuf + SBUF / 2 + arow0 + 16 * SROW + alo + ak);
#pragma unroll
                for (int p = 0; p < 4; p++) {
                    uint32_t boff = (uint32_t)((cg * 64 + p * 16 + bnl) * (SSTR * 2)) + wk;
                    uint32_t bh0, bh1, bh2, bh3, bl0, bl1, bl2, bl3;
                    ldm_x4(bh0, bh1, bh2, bh3, sb + SM_WH + boff);
                    ldm_x4(bl0, bl1, bl2, bl3, sb + SM_WL + boff);
                    float* a00 = acc[p * 2];
                    float* a01 = acc[p * 2 + 1];
                    float* a10 = acc[8 + p * 2];
                    float* a11 = acc[8 + p * 2 + 1];
                    mma16816(a00, ah0, bh0, bh1);
                    mma16816(a01, ah0, bh2, bh3);
                    mma16816(a10, ah1, bh0, bh1);
                    mma16816(a11, ah1, bh2, bh3);
                    mma16816(a00, ah0, bl0, bl1);
                    mma16816(a01, ah0, bl2, bl3);
                    mma16816(a10, ah1, bl0, bl1);
                    mma16816(a11, ah1, bl2, bl3);
                    mma16816(a00, al0, bh0, bh1);
                    mma16816(a01, al0, bh2, bh3);
                    mma16816(a10, al1, bh0, bh1);
                    mma16816(a11, al1, bh2, bh3);
                }
            }
            __syncthreads();                   // buffer fully consumed
            if (c < 2) {                       // refill with chunk c+2
                uint32_t dst = sb + SM_S + (uint32_t)(c & 1) * SBUF;
                for (int i = tid; i < 512; i += 256) {
                    int row = i >> 2, ch = (i & 3) * 16;
                    cpa16(dst + row * SROW + ch, shp + row * 256 + (c + 2) * 64 + ch);
                    cpa16(dst + SBUF / 2 + row * SROW + ch, slp + row * 256 + (c + 2) * 64 + ch);
                }
                CPA_COMMIT();
            }
        }

        // ---- epilogue: bias + relu + scatter
#pragma unroll
        for (int half = 0; half < 2; half++) {
            int r0 = rg * 32 + half * 16 + (lid >> 2);
            int r1 = r0 + 8;
            bool ok0 = (tb + r0) < pe;
            bool ok1 = (tb + r1) < pe;
            float* op0 = out + (size_t)snode[r0] * FF;
            float* op1 = out + (size_t)snode[r1] * FF;
#pragma unroll
            for (int p = 0; p < 4; p++) {
#pragma unroll
                for (int j = 0; j < 2; j++) {
                    int cc = cg * 64 + p * 16 + j * 8 + cb;
                    float b0 = sbias[cc], b1 = sbias[cc + 1];
                    float* a = acc[half * 8 + p * 2 + j];
                    if (ok0) {
                        float x0 = fmaxf(a[0] + b0, 0.f);
                        float x1 = fmaxf(a[1] + b1, 0.f);
                        *(float2*)(op0 + cc) = make_float2(x0, x1);
                    }
                    if (ok1) {
                        float x2 = fmaxf(a[2] + b0, 0.f);
                        float x3 = fmaxf(a[3] + b1, 0.f);
                        *(float2*)(op1 + cc) = make_float2(x2, x3);
                    }
                }
            }
        }
    }
}

// ===================== launch =====================
extern "C" void kernel_launch(void* const* d_in, const int* in_sizes, int n_in,
                              void* d_out, int out_size) {
    const float* atoms = (const float*)d_in[0];
    const int*   edges = (const int*)d_in[1];
    const float* W     = (const float*)d_in[2];
    const float* bias  = (const float*)d_in[3];
    float*       out   = (float*)d_out;

    cudaFuncSetAttribute(k_mma, cudaFuncAttributeMaxDynamicSharedMemorySize, SM_BYTES);

    void* cnt_ptr = nullptr;
    cudaGetSymbolAddress(&cnt_ptr, g_cnt);
    cudaMemsetAsync(cnt_ptr, 0, MAXDEG * sizeof(int));

    k_prep<<<448, 512>>>(edges, W);
    k_gather<<<SLOTS / 16, 256>>>(atoms, edges);   // 8 warps/block x 2 slots/warp
    k_mma<<<MMA_CTAS, 256, SM_BYTES>>>(bias, out);
}